// round 11
// baseline (speedup 1.0000x reference)
#include <cuda_runtime.h>
#include <cuda_fp16.h>
#include <math.h>
#include <stdint.h>

// Problem shape (fixed): B=512, L=512, D=256, fp32.
#define BATCH 512
#define LDIM  512
#define DDIM  256

// smem: 2 stages x (A 8KB + B 8KB) fp16 tiles + r1/r2 (128 f32 each)
#define ATILE_B 8192
#define STG_B   16384
#define R1_B    32768
#define R2_B    33280
#define SMEM_BYTES 33792

__device__ __forceinline__ uint32_t smem_u32(const void* p) {
    uint32_t a;
    asm("{ .reg .u64 t; cvta.to.shared.u64 t, %1; cvt.u32.u64 %0, t; }" : "=r"(a) : "l"(p));
    return a;
}
__device__ __forceinline__ float fsqrt_fast(float x) {
    float y; asm("sqrt.approx.f32 %0, %1;" : "=f"(y) : "f"(x)); return y;
}
#define LDS64(v, addr) \
    asm volatile("ld.shared.v2.b32 {%0,%1}, [%2];" : "=r"((v).x), "=r"((v).y) : "r"(addr))
#define STS128(addr, v) \
    asm volatile("st.shared.v4.b32 [%0], {%1,%2,%3,%4};" \
                 :: "r"(addr), "r"((v).x), "r"((v).y), "r"((v).z), "r"((v).w))

__device__ __forceinline__ void mma_f16(float* c,
                                        uint32_t a0, uint32_t a1, uint32_t a2, uint32_t a3,
                                        uint32_t b0, uint32_t b1) {
    asm volatile(
        "mma.sync.aligned.m16n8k16.row.col.f32.f16.f16.f32 "
        "{%0,%1,%2,%3}, {%4,%5,%6,%7}, {%8,%9}, {%0,%1,%2,%3};"
        : "+f"(c[0]), "+f"(c[1]), "+f"(c[2]), "+f"(c[3])
        : "r"(a0), "r"(a1), "r"(a2), "r"(a3), "r"(b0), "r"(b1));
}

__device__ __forceinline__ uint4 pack8(const float4 a, const float4 b) {
    __half2 h0 = __floats2half2_rn(a.x, a.y);
    __half2 h1 = __floats2half2_rn(a.z, a.w);
    __half2 h2 = __floats2half2_rn(b.x, b.y);
    __half2 h3 = __floats2half2_rn(b.z, b.w);
    uint4 u;
    u.x = *reinterpret_cast<uint32_t*>(&h0);
    u.y = *reinterpret_cast<uint32_t*>(&h1);
    u.z = *reinterpret_cast<uint32_t*>(&h2);
    u.w = *reinterpret_cast<uint32_t*>(&h3);
    return u;
}
__device__ __forceinline__ float sq4(const float4 v, float s) {
    s = fmaf(v.x, v.x, s); s = fmaf(v.y, v.y, s);
    s = fmaf(v.z, v.z, s); s = fmaf(v.w, v.w, s);
    return s;
}

// ---------------------------------------------------------------------------
// Single fused kernel: fp32 -> fp16 convert + norms inline, fp16 m16n8k16 GEMM.
// CTA tile 128x128, 8 chunks of k32, double-buffered swizzled fp16 smem.
// ---------------------------------------------------------------------------
__global__ __launch_bounds__(256, 2)
void dist_kernel(const float* __restrict__ A, const float* __restrict__ B,
                 float* __restrict__ out) {
    extern __shared__ char smem[];
    const uint32_t sb = smem_u32(smem);
    float* smf = reinterpret_cast<float*>(smem);

    const int tid = threadIdx.x;
    const int wid = tid >> 5, lid = tid & 31;
    const int b  = blockIdx.z;
    const int m0 = blockIdx.y * 128;
    const int n0 = blockIdx.x * 128;

    // ---- fill mapping: 2 threads per row; thread h covers 16B chunks {h, h+2}
    const int crow = tid >> 1;
    const int h    = tid & 1;
    const float* Ap = A + ((size_t)(b * LDIM + m0 + crow)) * DDIM + 8 * h;
    const float* Bp = B + ((size_t)(b * LDIM + n0 + crow)) * DDIM + 8 * h;
    const int k16 = (((crow >> 1) & 1) << 1) | ((crow >> 3) & 1);
    const uint32_t fA0 = sb + (uint32_t)(crow * 64 + (((h)     ^ k16) << 4));
    const uint32_t fA1 = sb + (uint32_t)(crow * 64 + (((h + 2) ^ k16) << 4));
    const uint32_t fB0 = fA0 + ATILE_B;
    const uint32_t fB1 = fA1 + ATILE_B;

    // ---- compute mapping: 2x4 warp grid, 64x32 warp tiles ----
    const int wm = wid >> 2, wn = wid & 3;
    const int g = lid >> 2, tig = lid & 3;

    // frag base addresses (k16 block 0); block 1 = addr ^ 32
    uint32_t aAddr[4][2], bAddr[4];
#pragma unroll
    for (int mt = 0; mt < 4; mt++) {
#pragma unroll
        for (int hi = 0; hi < 2; hi++) {
            int r = wm * 64 + mt * 16 + g + 8 * hi;
            int key = (((r >> 1) & 1) << 2) | (((r >> 3) & 1) << 1);
            aAddr[mt][hi] = sb + (uint32_t)(r * 64 + ((tig ^ key) << 3));
        }
    }
#pragma unroll
    for (int nt = 0; nt < 4; nt++) {
        int r = wn * 32 + nt * 8 + g;
        int key = (((r >> 1) & 1) << 2) | (((r >> 3) & 1) << 1);
        bAddr[nt] = sb + ATILE_B + (uint32_t)(r * 64 + ((tig ^ key) << 3));
    }

    float acc[4][4][4];
#pragma unroll
    for (int mt = 0; mt < 4; mt++)
#pragma unroll
        for (int nt = 0; nt < 4; nt++)
#pragma unroll
            for (int r = 0; r < 4; r++) acc[mt][nt][r] = 0.f;

    float ssa = 0.f, ssb = 0.f;
    float4 av[4], bv[4];

    // ---- prologue: chunk 0 ----
    av[0] = *reinterpret_cast<const float4*>(Ap + 0);
    av[1] = *reinterpret_cast<const float4*>(Ap + 4);
    av[2] = *reinterpret_cast<const float4*>(Ap + 16);
    av[3] = *reinterpret_cast<const float4*>(Ap + 20);
    bv[0] = *reinterpret_cast<const float4*>(Bp + 0);
    bv[1] = *reinterpret_cast<const float4*>(Bp + 4);
    bv[2] = *reinterpret_cast<const float4*>(Bp + 16);
    bv[3] = *reinterpret_cast<const float4*>(Bp + 20);
    ssa = sq4(av[0], ssa); ssa = sq4(av[1], ssa); ssa = sq4(av[2], ssa); ssa = sq4(av[3], ssa);
    ssb = sq4(bv[0], ssb); ssb = sq4(bv[1], ssb); ssb = sq4(bv[2], ssb); ssb = sq4(bv[3], ssb);
    { uint4 u = pack8(av[0], av[1]); STS128(fA0, u); }
    { uint4 u = pack8(av[2], av[3]); STS128(fA1, u); }
    { uint4 u = pack8(bv[0], bv[1]); STS128(fB0, u); }
    { uint4 u = pack8(bv[2], bv[3]); STS128(fB1, u); }
    __syncthreads();

#pragma unroll 1
    for (int kt = 0; kt < 8; kt++) {
        const uint32_t so = (uint32_t)((kt & 1) * STG_B);

        if (kt < 7) {
            const int cb = (kt + 1) * 32;
            av[0] = *reinterpret_cast<const float4*>(Ap + cb + 0);
            av[1] = *reinterpret_cast<const float4*>(Ap + cb + 4);
            av[2] = *reinterpret_cast<const float4*>(Ap + cb + 16);
            av[3] = *reinterpret_cast<const float4*>(Ap + cb + 20);
            bv[0] = *reinterpret_cast<const float4*>(Bp + cb + 0);
            bv[1] = *reinterpret_cast<const float4*>(Bp + cb + 4);
            bv[2] = *reinterpret_cast<const float4*>(Bp + cb + 16);
            bv[3] = *reinterpret_cast<const float4*>(Bp + cb + 20);
        }

        // ---- MMA: 2 k16 blocks ----
#pragma unroll
        for (int blk = 0; blk < 2; blk++) {
            const uint32_t xb = (uint32_t)(blk << 5);
            uint2 bf[4];
#pragma unroll
            for (int nt = 0; nt < 4; nt++)
                LDS64(bf[nt], (bAddr[nt] + so) ^ xb);
#pragma unroll
            for (int mt = 0; mt < 4; mt++) {
                uint2 alo, ahi;
                LDS64(alo, (aAddr[mt][0] + so) ^ xb);
                LDS64(ahi, (aAddr[mt][1] + so) ^ xb);
#pragma unroll
                for (int nt = 0; nt < 4; nt++)
                    mma_f16(acc[mt][nt], alo.x, ahi.x, alo.y, ahi.y, bf[nt].x, bf[nt].y);
            }
        }

        if (kt < 7) {
            const uint32_t sn = (uint32_t)(((kt + 1) & 1) * STG_B);
            ssa = sq4(av[0], ssa); ssa = sq4(av[1], ssa);
            ssa = sq4(av[2], ssa); ssa = sq4(av[3], ssa);
            ssb = sq4(bv[0], ssb); ssb = sq4(bv[1], ssb);
            ssb = sq4(bv[2], ssb); ssb = sq4(bv[3], ssb);
            { uint4 u = pack8(av[0], av[1]); STS128(fA0 + sn, u); }
            { uint4 u = pack8(av[2], av[3]); STS128(fA1 + sn, u); }
            { uint4 u = pack8(bv[0], bv[1]); STS128(fB0 + sn, u); }
            { uint4 u = pack8(bv[2], bv[3]); STS128(fB1 + sn, u); }
            __syncthreads();
        }
    }

    // ---- norms: combine pair (tid, tid^1), publish ----
    ssa += __shfl_xor_sync(0xffffffffu, ssa, 1);
    ssb += __shfl_xor_sync(0xffffffffu, ssb, 1);
    if (h == 0) {
        smf[(R1_B >> 2) + crow] = ssa;
        smf[(R2_B >> 2) + crow] = ssb;
    }
    __syncthreads();

    // ---- epilogue: d = sqrt(max(r1 + r2 - 2*dot, 0)) ----
    const int klane = 2 * tig;
    const float* R1 = smf + (R1_B >> 2);
    const float* R2 = smf + (R2_B >> 2);
    float r1v[4][2];
#pragma unroll
    for (int mt = 0; mt < 4; mt++) {
        r1v[mt][0] = R1[wm * 64 + mt * 16 + g];
        r1v[mt][1] = R1[wm * 64 + mt * 16 + g + 8];
    }
    float2 r2v[4];
#pragma unroll
    for (int nt = 0; nt < 4; nt++)
        r2v[nt] = *reinterpret_cast<const float2*>(R2 + wn * 32 + nt * 8 + klane);

    float* Ob = out + ((size_t)(b * LDIM + m0)) * LDIM + n0;
#pragma unroll
    for (int mt = 0; mt < 4; mt++) {
#pragma unroll
        for (int nt = 0; nt < 4; nt++) {
            const int col  = wn * 32 + nt * 8 + klane;
            const int row0 = wm * 64 + mt * 16 + g;
            float2 v0, v1;
            v0.x = fsqrt_fast(fmaxf(r1v[mt][0] + r2v[nt].x - 2.0f * acc[mt][nt][0], 0.f));
            v0.y = fsqrt_fast(fmaxf(r1v[mt][0] + r2v[nt].y - 2.0f * acc[mt][nt][1], 0.f));
            v1.x = fsqrt_fast(fmaxf(r1v[mt][1] + r2v[nt].x - 2.0f * acc[mt][nt][2], 0.f));
            v1.y = fsqrt_fast(fmaxf(r1v[mt][1] + r2v[nt].y - 2.0f * acc[mt][nt][3], 0.f));
            *reinterpret_cast<float2*>(Ob + (size_t)row0 * LDIM + col)       = v0;
            *reinterpret_cast<float2*>(Ob + (size_t)(row0 + 8) * LDIM + col) = v1;
        }
    }
}

// ---------------------------------------------------------------------------
extern "C" void kernel_launch(void* const* d_in, const int* in_sizes, int n_in,
                              void* d_out, int out_size) {
    const float* A = (const float*)d_in[0];
    const float* B = (const float*)d_in[1];
    float* out = (float*)d_out;
    (void)in_sizes; (void)n_in; (void)out_size;

    cudaFuncSetAttribute(dist_kernel,
                         cudaFuncAttributeMaxDynamicSharedMemorySize, SMEM_BYTES);
    dim3 grid(LDIM / 128, LDIM / 128, BATCH);
    dist_kernel<<<grid, 256, SMEM_BYTES>>>(A, B, out);
}

// round 12
// speedup vs baseline: 1.0254x; 1.0254x over previous
#include <cuda_runtime.h>
#include <cuda_fp16.h>
#include <math.h>
#include <stdint.h>

// Problem shape (fixed): B=512, L=512, D=256, fp32.
#define BATCH 512
#define LDIM  512
#define DDIM  256

// smem: 2 stages x (A 8KB + B 8KB) fp16 tiles (rows 64B) + r1/r2
#define ATILE_B 8192
#define STG_B   16384
#define R1_B    32768
#define R2_B    33280
#define SMEM_BYTES 33792      // 33KB -> 2 CTAs/SM easily

__device__ __forceinline__ uint32_t smem_u32(const void* p) {
    uint32_t a;
    asm("{ .reg .u64 t; cvta.to.shared.u64 t, %1; cvt.u32.u64 %0, t; }" : "=r"(a) : "l"(p));
    return a;
}
__device__ __forceinline__ float fsqrt_fast(float x) {
    float y; asm("sqrt.approx.f32 %0, %1;" : "=f"(y) : "f"(x)); return y;
}
#define LDS64(v, addr) \
    asm volatile("ld.shared.v2.b32 {%0,%1}, [%2];" : "=r"((v).x), "=r"((v).y) : "r"(addr))
#define STS64(addr, r0, r1) \
    asm volatile("st.shared.v2.b32 [%0], {%1,%2};" :: "r"(addr), "r"(r0), "r"(r1))

__device__ __forceinline__ void mma_f16(float* c,
                                        uint32_t a0, uint32_t a1, uint32_t a2, uint32_t a3,
                                        uint32_t b0, uint32_t b1) {
    asm volatile(
        "mma.sync.aligned.m16n8k16.row.col.f32.f16.f16.f32 "
        "{%0,%1,%2,%3}, {%4,%5,%6,%7}, {%8,%9}, {%0,%1,%2,%3};"
        : "+f"(c[0]), "+f"(c[1]), "+f"(c[2]), "+f"(c[3])
        : "r"(a0), "r"(a1), "r"(a2), "r"(a3), "r"(b0), "r"(b1));
}

__device__ __forceinline__ float sq4(const float4 v, float s) {
    s = fmaf(v.x, v.x, s); s = fmaf(v.y, v.y, s);
    s = fmaf(v.z, v.z, s); s = fmaf(v.w, v.w, s);
    return s;
}
// float4 -> 8B fp16 pair
__device__ __forceinline__ void cvt8(const float4 v, uint32_t& lo, uint32_t& hi) {
    __half2 a = __floats2half2_rn(v.x, v.y);
    __half2 b = __floats2half2_rn(v.z, v.w);
    lo = *reinterpret_cast<uint32_t*>(&a);
    hi = *reinterpret_cast<uint32_t*>(&b);
}

// ---------------------------------------------------------------------------
// Fused: fp32 LDG + fp16 convert + norms inline, fp16 m16n8k16 GEMM.
// CTA tile 128x128, 8 chunks of k32, double-buffered swizzled fp16 smem.
// Swizzle: 16B unit j of row r stored at j ^ ((r>>1)&3).
// ---------------------------------------------------------------------------
__global__ __launch_bounds__(256, 2)
void dist_kernel(const float* __restrict__ A, const float* __restrict__ B,
                 float* __restrict__ out) {
    extern __shared__ char smem[];
    const uint32_t sb = smem_u32(smem);
    float* smf = reinterpret_cast<float*>(smem);

    const int tid = threadIdx.x;
    const int wid = tid >> 5, lid = tid & 31;
    const int b  = blockIdx.z;
    const int m0 = blockIdx.y * 128;
    const int n0 = blockIdx.x * 128;

    // ---- fill mapping: 2 threads/row; thread h owns 16B units u = 2j+h ----
    const int crow = tid >> 1;
    const int h    = tid & 1;
    const int keyc = (crow >> 1) & 3;
    const float* Ap = A + ((size_t)(b * LDIM + m0 + crow)) * DDIM;
    const float* Bp = B + ((size_t)(b * LDIM + n0 + crow)) * DDIM;
    // STS addresses for j=0..3: row*64 + (j^keyc)*16 + h*8
    uint32_t stA[4];
#pragma unroll
    for (int j = 0; j < 4; j++)
        stA[j] = sb + (uint32_t)(crow * 64 + ((j ^ keyc) << 4) + (h << 3));

    // ---- compute mapping: 2x4 warp grid, 64x32 warp tiles ----
    const int wm = wid >> 2, wn = wid & 3;
    const int g = lid >> 2, tig = lid & 3;

    // frag addresses: row r, k16 block blk -> row*64 + (((2blk+(tig>>1))^key16(r))<<4) + (tig&1)*8
    const int tq = tig >> 1, tb = (tig & 1) << 3;
    uint32_t aAddr[4][2][2], bAddr[4][2];   // [mt][hi][blk], [nt][blk]
#pragma unroll
    for (int mt = 0; mt < 4; mt++)
#pragma unroll
        for (int hi = 0; hi < 2; hi++) {
            int r = wm * 64 + mt * 16 + g + 8 * hi;
            int key = (r >> 1) & 3;
#pragma unroll
            for (int blk = 0; blk < 2; blk++)
                aAddr[mt][hi][blk] = sb + (uint32_t)(r * 64 + (((2 * blk + tq) ^ key) << 4) + tb);
        }
#pragma unroll
    for (int nt = 0; nt < 4; nt++) {
        int r = wn * 32 + nt * 8 + g;
        int key = (r >> 1) & 3;
#pragma unroll
        for (int blk = 0; blk < 2; blk++)
            bAddr[nt][blk] = sb + ATILE_B + (uint32_t)(r * 64 + (((2 * blk + tq) ^ key) << 4) + tb);
    }

    float acc[4][4][4];
#pragma unroll
    for (int mt = 0; mt < 4; mt++)
#pragma unroll
        for (int nt = 0; nt < 4; nt++)
#pragma unroll
            for (int r = 0; r < 4; r++) acc[mt][nt][r] = 0.f;

    float ssa = 0.f, ssb = 0.f;
    float4 av[4], bv[4];

    // ---- prologue: chunk 0 -> buffer 0 ----
#pragma unroll
    for (int j = 0; j < 4; j++) {
        av[j] = *reinterpret_cast<const float4*>(Ap + (2 * j + h) * 4);
        bv[j] = *reinterpret_cast<const float4*>(Bp + (2 * j + h) * 4);
    }
#pragma unroll
    for (int j = 0; j < 4; j++) {
        ssa = sq4(av[j], ssa); ssb = sq4(bv[j], ssb);
        uint32_t lo, hi;
        cvt8(av[j], lo, hi); STS64(stA[j], lo, hi);
        cvt8(bv[j], lo, hi); STS64(stA[j] + ATILE_B, lo, hi);
    }
    __syncthreads();

#pragma unroll 1
    for (int kt = 0; kt < 8; kt++) {
        const uint32_t so = (uint32_t)((kt & 1) * STG_B);

        if (kt < 7) {
            const int cb = (kt + 1) * 32;
#pragma unroll
            for (int j = 0; j < 4; j++) {
                av[j] = *reinterpret_cast<const float4*>(Ap + cb + (2 * j + h) * 4);
                bv[j] = *reinterpret_cast<const float4*>(Bp + cb + (2 * j + h) * 4);
            }
        }

        // ---- MMA: 2 k16 blocks ----
#pragma unroll
        for (int blk = 0; blk < 2; blk++) {
            uint2 bf[4];
#pragma unroll
            for (int nt = 0; nt < 4; nt++)
                LDS64(bf[nt], bAddr[nt][blk] + so);
#pragma unroll
            for (int mt = 0; mt < 4; mt++) {
                uint2 alo, ahi;
                LDS64(alo, aAddr[mt][0][blk] + so);
                LDS64(ahi, aAddr[mt][1][blk] + so);
#pragma unroll
                for (int nt = 0; nt < 4; nt++)
                    mma_f16(acc[mt][nt], alo.x, ahi.x, alo.y, ahi.y, bf[nt].x, bf[nt].y);
            }
        }

        if (kt < 7) {
            const uint32_t sn = (uint32_t)(((kt + 1) & 1) * STG_B);
#pragma unroll
            for (int j = 0; j < 4; j++) {
                ssa = sq4(av[j], ssa); ssb = sq4(bv[j], ssb);
                uint32_t lo, hi;
                cvt8(av[j], lo, hi); STS64(stA[j] + sn, lo, hi);
                cvt8(bv[j], lo, hi); STS64(stA[j] + sn + ATILE_B, lo, hi);
            }
            __syncthreads();
        }
    }

    // ---- norms: combine pair (tid, tid^1), publish ----
    ssa += __shfl_xor_sync(0xffffffffu, ssa, 1);
    ssb += __shfl_xor_sync(0xffffffffu, ssb, 1);
    __syncthreads();   // ensure all MMA reads done before tile smem reuse conceptually; r1/r2 area is separate but keep ordering cheap
    if (h == 0) {
        smf[(R1_B >> 2) + crow] = ssa;
        smf[(R2_B >> 2) + crow] = ssb;
    }
    __syncthreads();

    // ---- epilogue: d = sqrt(max(r1 + r2 - 2*dot, 0)) ----
    const int klane = 2 * tig;
    const float* R1 = smf + (R1_B >> 2);
    const float* R2 = smf + (R2_B >> 2);
    float r1v[4][2];
#pragma unroll
    for (int mt = 0; mt < 4; mt++) {
        r1v[mt][0] = R1[wm * 64 + mt * 16 + g];
        r1v[mt][1] = R1[wm * 64 + mt * 16 + g + 8];
    }
    float2 r2v[4];
#pragma unroll
    for (int nt = 0; nt < 4; nt++)
        r2v[nt] = *reinterpret_cast<const float2*>(R2 + wn * 32 + nt * 8 + klane);

    float* Ob = out + ((size_t)(b * LDIM + m0)) * LDIM + n0;
#pragma unroll
    for (int mt = 0; mt < 4; mt++) {
#pragma unroll
        for (int nt = 0; nt < 4; nt++) {
            const int col  = wn * 32 + nt * 8 + klane;
            const int row0 = wm * 64 + mt * 16 + g;
            float2 v0, v1;
            v0.x = fsqrt_fast(fmaxf(r1v[mt][0] + r2v[nt].x - 2.0f * acc[mt][nt][0], 0.f));
            v0.y = fsqrt_fast(fmaxf(r1v[mt][0] + r2v[nt].y - 2.0f * acc[mt][nt][1], 0.f));
            v1.x = fsqrt_fast(fmaxf(r1v[mt][1] + r2v[nt].x - 2.0f * acc[mt][nt][2], 0.f));
            v1.y = fsqrt_fast(fmaxf(r1v[mt][1] + r2v[nt].y - 2.0f * acc[mt][nt][3], 0.f));
            *reinterpret_cast<float2*>(Ob + (size_t)row0 * LDIM + col)       = v0;
            *reinterpret_cast<float2*>(Ob + (size_t)(row0 + 8) * LDIM + col) = v1;
        }
    }
}

// ---------------------------------------------------------------------------
extern "C" void kernel_launch(void* const* d_in, const int* in_sizes, int n_in,
                              void* d_out, int out_size) {
    const float* A = (const float*)d_in[0];
    const float* B = (const float*)d_in[1];
    float* out = (float*)d_out;
    (void)in_sizes; (void)n_in; (void)out_size;

    cudaFuncSetAttribute(dist_kernel,
                         cudaFuncAttributeMaxDynamicSharedMemorySize, SMEM_BYTES);
    dim3 grid(LDIM / 128, LDIM / 128, BATCH);
    dist_kernel<<<grid, 256, SMEM_BYTES>>>(A, B, out);
}

// round 13
// speedup vs baseline: 1.7552x; 1.7116x over previous
#include <cuda_runtime.h>
#include <cuda_fp16.h>
#include <math.h>
#include <stdint.h>

// Problem shape (fixed): B=512, L=512, D=256, fp32.
#define BATCH 512
#define LDIM  512
#define DDIM  256
#define EPSV  1e-6f

#define NSLICE 4
#define BSLICE (BATCH/NSLICE)        // 128 batches per slice

// ---------------- scratch (device globals; allocation-free) ----------------
__device__ unsigned short g_A16[(size_t)BATCH * LDIM * DDIM];  // 134MB, pre-swizzled fp16
__device__ unsigned short g_B16[(size_t)BATCH * LDIM * DDIM];  // 134MB
__device__ float g_r1[BATCH * LDIM];
__device__ float g_r2[BATCH * LDIM];

// ---------------- helpers ----------------
__device__ __forceinline__ uint32_t smem_u32(const void* p) {
    uint32_t a;
    asm("{ .reg .u64 t; cvta.to.shared.u64 t, %1; cvt.u32.u64 %0, t; }" : "=r"(a) : "l"(p));
    return a;
}
__device__ __forceinline__ float fsqrt_fast(float x) {
    float y; asm("sqrt.approx.f32 %0, %1;" : "=f"(y) : "f"(x)); return y;
}
__device__ __forceinline__ void cp16(uint32_t saddr, const void* g) {
    asm volatile("cp.async.cg.shared.global [%0], [%1], 16;" :: "r"(saddr), "l"(g));
}
__device__ __forceinline__ void cp_commit() { asm volatile("cp.async.commit_group;"); }
__device__ __forceinline__ void cp_wait1()  { asm volatile("cp.async.wait_group 1;" ::: "memory"); }
__device__ __forceinline__ void cp_wait0()  { asm volatile("cp.async.wait_group 0;" ::: "memory"); }

#define LDS64(v, addr) \
    asm volatile("ld.shared.v2.b32 {%0,%1}, [%2];" : "=r"((v).x), "=r"((v).y) : "r"(addr))

__device__ __forceinline__ void mma_f16(float* c,
                                        uint32_t a0, uint32_t a1, uint32_t a2, uint32_t a3,
                                        uint32_t b0, uint32_t b1) {
    asm volatile(
        "mma.sync.aligned.m16n8k16.row.col.f32.f16.f16.f32 "
        "{%0,%1,%2,%3}, {%4,%5,%6,%7}, {%8,%9}, {%0,%1,%2,%3};"
        : "+f"(c[0]), "+f"(c[1]), "+f"(c[2]), "+f"(c[3])
        : "r"(a0), "r"(a1), "r"(a2), "r"(a3), "r"(b0), "r"(b1));
}

// ---------------------------------------------------------------------------
// Pre-pass (sliced): one warp per row over batches [batch0, batch0+BSLICE).
// Exact fp32 norms + fp16 conversion with tile swizzle pre-applied
// (8B-chunk c -> c ^ key(row), key = ((r&3)<<2)|(((r>>2)&1)<<1), per 128B section).
// Low-reg (<=32) so it co-resides with GEMM CTAs.
// ---------------------------------------------------------------------------
__global__ __launch_bounds__(256, 8)
void prep_kernel(const float* __restrict__ A, const float* __restrict__ B,
                 int batch0) {
    const int gw   = (int)((blockIdx.x * 256 + threadIdx.x) >> 5);
    const int lane = threadIdx.x & 31;
    const int rows = BSLICE * LDIM;                 // per tensor per slice
    const int isB  = (gw >= rows);
    const int row  = batch0 * LDIM + (isB ? gw - rows : gw);

    const float* src = (isB ? B : A) + (size_t)row * DDIM + lane * 8;
    float4 v0 = *reinterpret_cast<const float4*>(src);
    float4 v1 = *reinterpret_cast<const float4*>(src + 4);

    float ss = 0.f, s = 0.f;
    ss = fmaf(v0.x, v0.x, ss); ss = fmaf(v0.y, v0.y, ss);
    ss = fmaf(v0.z, v0.z, ss); ss = fmaf(v0.w, v0.w, ss);
    ss = fmaf(v1.x, v1.x, ss); ss = fmaf(v1.y, v1.y, ss);
    ss = fmaf(v1.z, v1.z, ss); ss = fmaf(v1.w, v1.w, ss);
    s = v0.x + v0.y + v0.z + v0.w + v1.x + v1.y + v1.z + v1.w;
#pragma unroll
    for (int off = 16; off > 0; off >>= 1) {
        ss += __shfl_xor_sync(0xffffffffu, ss, off);
        s  += __shfl_xor_sync(0xffffffffu, s, off);
    }
    if (lane == 0) {
        if (isB) g_r2[row] = ss - 2.0f * EPSV * s + (float)DDIM * EPSV * EPSV;
        else     g_r1[row] = ss + 2.0f * EPSV * s;
    }

    __half2 h0 = __floats2half2_rn(v0.x, v0.y);
    __half2 h1 = __floats2half2_rn(v0.z, v0.w);
    __half2 h2 = __floats2half2_rn(v1.x, v1.y);
    __half2 h3 = __floats2half2_rn(v1.z, v1.w);
    uint4 pk;
    pk.x = *reinterpret_cast<uint32_t*>(&h0);
    pk.y = *reinterpret_cast<uint32_t*>(&h1);
    pk.z = *reinterpret_cast<uint32_t*>(&h2);
    pk.w = *reinterpret_cast<uint32_t*>(&h3);

    const int key = ((row & 3) << 2) | (((row >> 2) & 1) << 1);
    const int sec = lane >> 3;
    const int ci  = (2 * lane) & 15;
    char* dst = (char*)(isB ? g_B16 : g_A16) + (size_t)row * 512 + sec * 128 + ((ci ^ key) << 3);
    *reinterpret_cast<uint4*>(dst) = pk;
}

// ---------------------------------------------------------------------------
// Main (sliced): fp16 m16n8k16 GEMM, 128x128 CTA tile, k64 chunks, 3-stage cp.async.
// Identical to the proven round-8 kernel, plus a batch offset.
// ---------------------------------------------------------------------------
#define TILEB 16384
#define STGB  (2*TILEB)
#define SMEM_BYTES (3*STGB)   // 98304 -> 2 CTAs/SM

__global__ __launch_bounds__(256, 2)
void dist_f16_kernel(float* __restrict__ out, int batch0) {
    extern __shared__ char smem[];
    const uint32_t sb = smem_u32(smem);

    const int tid = threadIdx.x;
    const int wid = tid >> 5, lid = tid & 31;
    const int b  = batch0 + blockIdx.z;
    const int m0 = blockIdx.y * 128;
    const int n0 = blockIdx.x * 128;

    // ---- cp.async mapping: thread -> (row tid>>3 + 32t, 16B chunk tid&7) ----
    const int crow = tid >> 3;
    const int cc   = tid & 7;
    const char* Asrc = (const char*)g_A16 + (size_t)(b * LDIM + m0 + crow) * 512 + cc * 16;
    const char* Bsrc = (const char*)g_B16 + (size_t)(b * LDIM + n0 + crow) * 512 + cc * 16;
    const uint32_t sdst = sb + (uint32_t)(crow * 128 + cc * 16);

    // ---- compute mapping: 2x4 warp grid, 64x32 warp tiles ----
    const int wm = wid >> 2, wn = wid & 3;
    const int g = lid >> 2, tig = lid & 3;
    const int arow0 = wm * 64 + g;
    const int brow0 = wn * 32 + g;
    const int txa = (tig ^ (((g >> 2) & 1) << 1)) << 3;
    const int gl2 = g & 3;
    const uint32_t aBase = sb + (uint32_t)(arow0 * 128 + txa);
    const uint32_t bBase = sb + TILEB + (uint32_t)(brow0 * 128 + txa);

    float acc[4][4][4];
#pragma unroll
    for (int mt = 0; mt < 4; mt++)
#pragma unroll
        for (int nt = 0; nt < 4; nt++)
#pragma unroll
            for (int r = 0; r < 4; r++) acc[mt][nt][r] = 0.f;

#pragma unroll
    for (int s = 0; s < 2; s++) {
#pragma unroll
        for (int t = 0; t < 4; t++) {
            cp16(sdst + s * STGB + t * 4096,         Asrc + (size_t)(t * 32) * 512 + s * 128);
            cp16(sdst + s * STGB + TILEB + t * 4096, Bsrc + (size_t)(t * 32) * 512 + s * 128);
        }
        cp_commit();
    }

#pragma unroll 1
    for (int kt = 0; kt < 4; kt++) {
        if (kt == 3) cp_wait0(); else cp_wait1();
        __syncthreads();

        if (kt + 2 < 4) {
            const uint32_t cs = (uint32_t)(((kt + 2) % 3) * STGB);
#pragma unroll
            for (int t = 0; t < 4; t++) {
                cp16(sdst + cs + t * 4096,         Asrc + (size_t)(t * 32) * 512 + (kt + 2) * 128);
                cp16(sdst + cs + TILEB + t * 4096, Bsrc + (size_t)(t * 32) * 512 + (kt + 2) * 128);
            }
            cp_commit();
        }

        const uint32_t so = (uint32_t)((kt % 3) * STGB);
        const uint32_t sA = aBase + so;
        const uint32_t sB = bBase + so;

#pragma unroll
        for (int blk = 0; blk < 4; blk++) {
            const uint32_t bo = (uint32_t)((blk ^ gl2) << 5);
            uint2 bf[4];
#pragma unroll
            for (int nt = 0; nt < 4; nt++)
                LDS64(bf[nt], sB + bo + nt * 8 * 128);
#pragma unroll
            for (int mt = 0; mt < 4; mt++) {
                uint2 alo, ahi;
                LDS64(alo, sA + bo + mt * 16 * 128);
                LDS64(ahi, sA + bo + mt * 16 * 128 + 8 * 128);
#pragma unroll
                for (int nt = 0; nt < 4; nt++)
                    mma_f16(acc[mt][nt], alo.x, ahi.x, alo.y, ahi.y, bf[nt].x, bf[nt].y);
            }
        }
    }

    // ---- epilogue ----
    const int klane = 2 * tig;
    const float* R1 = g_r1 + b * LDIM + m0;
    const float* R2 = g_r2 + b * LDIM + n0;
    float r1v[4][2];
#pragma unroll
    for (int mt = 0; mt < 4; mt++) {
        r1v[mt][0] = R1[wm * 64 + mt * 16 + g];
        r1v[mt][1] = R1[wm * 64 + mt * 16 + g + 8];
    }
    float2 r2v[4];
#pragma unroll
    for (int nt = 0; nt < 4; nt++)
        r2v[nt] = *reinterpret_cast<const float2*>(R2 + wn * 32 + nt * 8 + klane);

    float* Ob = out + ((size_t)(b * LDIM + m0)) * LDIM + n0;
#pragma unroll
    for (int mt = 0; mt < 4; mt++) {
#pragma unroll
        for (int nt = 0; nt < 4; nt++) {
            const int col  = wn * 32 + nt * 8 + klane;
            const int row0 = wm * 64 + mt * 16 + g;
            float2 v0, v1;
            v0.x = fsqrt_fast(fmaxf(r1v[mt][0] + r2v[nt].x - 2.0f * acc[mt][nt][0], 0.f));
            v0.y = fsqrt_fast(fmaxf(r1v[mt][0] + r2v[nt].y - 2.0f * acc[mt][nt][1], 0.f));
            v1.x = fsqrt_fast(fmaxf(r1v[mt][1] + r2v[nt].x - 2.0f * acc[mt][nt][2], 0.f));
            v1.y = fsqrt_fast(fmaxf(r1v[mt][1] + r2v[nt].y - 2.0f * acc[mt][nt][3], 0.f));
            *reinterpret_cast<float2*>(Ob + (size_t)row0 * LDIM + col)       = v0;
            *reinterpret_cast<float2*>(Ob + (size_t)(row0 + 8) * LDIM + col) = v1;
        }
    }
}

// ---------------------------------------------------------------------------
extern "C" void kernel_launch(void* const* d_in, const int* in_sizes, int n_in,
                              void* d_out, int out_size) {
    const float* A = (const float*)d_in[0];
    const float* B = (const float*)d_in[1];
    float* out = (float*)d_out;
    (void)in_sizes; (void)n_in; (void)out_size;

    // one-time stream/event setup (first call is the non-captured correctness run)
    static cudaStream_t side = nullptr;
    static cudaEvent_t eFork = nullptr;
    static cudaEvent_t eP[NSLICE];
    if (side == nullptr) {
        int lo, hi;
        cudaDeviceGetStreamPriorityRange(&lo, &hi);
        cudaStreamCreateWithPriority(&side, cudaStreamNonBlocking, hi);
        cudaEventCreateWithFlags(&eFork, cudaEventDisableTiming);
        for (int s = 0; s < NSLICE; s++)
            cudaEventCreateWithFlags(&eP[s], cudaEventDisableTiming);
    }

    static bool attrDone = false;
    if (!attrDone) {
        cudaFuncSetAttribute(dist_f16_kernel,
                             cudaFuncAttributeMaxDynamicSharedMemorySize, SMEM_BYTES);
        attrDone = true;
    }

    // fork side stream from the capture (legacy) stream
    cudaEventRecord(eFork, 0);
    cudaStreamWaitEvent(side, eFork, 0);

    // prep slices on side stream
    const int prepBlocks = (2 * BSLICE * LDIM) / 8;   // warps/8 per block
    for (int s = 0; s < NSLICE; s++) {
        prep_kernel<<<prepBlocks, 256, 0, side>>>(A, B, s * BSLICE);
        cudaEventRecord(eP[s], side);
    }

    // GEMM slices on the capture stream, each gated on its prep slice
    for (int s = 0; s < NSLICE; s++) {
        cudaStreamWaitEvent(0, eP[s], 0);
        dim3 grid(LDIM / 128, LDIM / 128, BSLICE);
        dist_f16_kernel<<<grid, 256, SMEM_BYTES>>>(out, s * BSLICE);
    }
}